// round 15
// baseline (speedup 1.0000x reference)
#include <cuda_runtime.h>
#include <cstdint>

// ---------------------------------------------------------------------------
// NeuralMJDFinancial: exact JAX (threefry-partitionable) reproduction.
// L=96, D=64, H=24, WID=256, K=1024, M=20. Output (K,H,D) f32.
//
// R15 = R14 (227.8us best) with phase 1b moved PRE-flag:
//  * loop 2 stays SEPARATE and lean (R13's merged loop blew L0 I$) and uses
//    compile-time BMIN superset compare (same 2-op body; no ballot - R12 bug)
//  * candidate compaction pre-flag; post-flag = packed pass A (recompute
//    candidate bits, exact b>bcut filter, bit-identical) + pass B with u1
//    from stored bits (deletes R14's per-event sk-threefry)
// ---------------------------------------------------------------------------

#define DD 64
#define HH 24
#define LL 96
#define WID 256
#define MM 20
#define NSUB 24
#define QMAX 192
#define NBLK 256
#define BMIN 0xF3000000u   // 0.94922*2^32 < e^-0.05*2^32 <= every bcut

__device__ float g_bufA[WID * DD];
__device__ float g_bufB[WID * DD];
__device__ float g_bufC[WID * DD];
__device__ float g_raw[HH * 5 * DD];
__device__ float g_mu[HH * DD];
__device__ float g_base[HH * DD];
__device__ float g_ssd[HH * DD];
__device__ float g_mlam[HH * DD];
__device__ unsigned g_bcut[HH * DD];   // exact decision: bits > bcut
__device__ float g_nu[HH * DD];
__device__ float g_gm[HH * DD];
__device__ float g_a20[HH * DD];
__device__ uint2 g_sub[NSUB + 2];
__device__ unsigned g_bar_cnt;
__device__ unsigned g_bar_gen;
__device__ unsigned g_flag;        // set once encoder results published
__device__ unsigned g_one = 1u;    // opaque 1: forces IMAD (fma pipe)

__device__ __forceinline__ unsigned imad(unsigned a, unsigned b, unsigned c) {
    unsigned r;
    asm("mad.lo.u32 %0, %1, %2, %3;" : "=r"(r) : "r"(a), "r"(b), "r"(c));
    return r;
}

// ---------------- Threefry-2x32, 20 rounds ----------------
#define TFRI(r) { x0 = imad(x1, one, x0); x1 = __funnelshift_l(x1, x1, (r)); x1 ^= x0; }

// hot variant: x0=0 entry folded (x0=k0, x1=e+k1 via IMAD on fma pipe)
__device__ __forceinline__ unsigned tf_bits_pre(unsigned k0, unsigned k1, unsigned k2,
                                                unsigned e, unsigned one) {
    unsigned x0 = k0;
    unsigned x1 = imad(k1, one, e);
    TFRI(13) TFRI(15) TFRI(26) TFRI(6)
    x0 = imad(k1, one, x0); x1 += k2 + 1u;
    TFRI(17) TFRI(29) TFRI(16) TFRI(24)
    x0 = imad(k2, one, x0); x1 += k0 + 2u;
    TFRI(13) TFRI(15) TFRI(26) TFRI(6)
    x0 = imad(k0, one, x0); x1 += k1 + 3u;
    TFRI(17) TFRI(29) TFRI(16) TFRI(24)
    x0 = imad(k1, one, x0); x1 += k2 + 4u;
    TFRI(13) TFRI(15) TFRI(26) TFRI(6)
    x0 = imad(k2, one, x0); x1 += k0 + 5u;
    return x0 ^ x1;
}

// plain variant (setup / cold / chain)
#define TFR(r) { x0 += x1; x1 = __funnelshift_l(x1, x1, (r)); x1 ^= x0; }

__device__ __forceinline__ uint2 tf2x32(unsigned k0, unsigned k1,
                                        unsigned x0, unsigned x1) {
    unsigned k2 = k0 ^ k1 ^ 0x1BD11BDAu;
    x0 += k0; x1 += k1;
    TFR(13) TFR(15) TFR(26) TFR(6)
    x0 += k1; x1 += k2 + 1u;
    TFR(17) TFR(29) TFR(16) TFR(24)
    x0 += k2; x1 += k0 + 2u;
    TFR(13) TFR(15) TFR(26) TFR(6)
    x0 += k0; x1 += k1 + 3u;
    TFR(17) TFR(29) TFR(16) TFR(24)
    x0 += k1; x1 += k2 + 4u;
    TFR(13) TFR(15) TFR(26) TFR(6)
    x0 += k2; x1 += k0 + 5u;
    return make_uint2(x0, x1);
}

__device__ __forceinline__ unsigned tf_bits(uint2 key, unsigned e) {
    uint2 r = tf2x32(key.x, key.y, 0u, e);
    return r.x ^ r.y;
}

// u01: (b>>9)|0x3f800000 bitcast - 1; shift as IMAD.HI (fma pipe), exact.
__device__ __forceinline__ float u01(unsigned b) {
    unsigned hi = __umulhi(b, 0x00800000u);   // == b >> 9
    return __uint_as_float(hi | 0x3f800000u) - 1.0f;
}

__device__ __forceinline__ float erfinv_common(float w) {
    float ww = w - 2.5f;
    float p = 2.81022636e-08f;
    p = fmaf(p, ww, 3.43273939e-07f);
    p = fmaf(p, ww, -3.5233877e-06f);
    p = fmaf(p, ww, -4.39150654e-06f);
    p = fmaf(p, ww, 0.00021858087f);
    p = fmaf(p, ww, -0.00125372503f);
    p = fmaf(p, ww, -0.00417768164f);
    p = fmaf(p, ww, 0.246640727f);
    p = fmaf(p, ww, 1.50140941f);
    return p;
}

__device__ __forceinline__ float erfinv_rare(float w) {
    float wr = sqrtf(w) - 3.0f;
    float q = -0.000200214257f;
    q = fmaf(q, wr, 0.000100950558f);
    q = fmaf(q, wr, 0.00134934322f);
    q = fmaf(q, wr, -0.00367342844f);
    q = fmaf(q, wr, 0.00573950773f);
    q = fmaf(q, wr, -0.0076224613f);
    q = fmaf(q, wr, 0.00943887047f);
    q = fmaf(q, wr, 1.00167406f);
    q = fmaf(q, wr, 2.83297682f);
    return q;
}

// diffusion normal WITHOUT sqrt2 (folded into epilogue). warp-converged only.
__device__ __forceinline__ float jnorm_px(unsigned bits) {
    const float LO = -0.99999994f;  // 0xBF7FFFFF
    float f = u01(bits);
    float x = fmaf(f, 2.0f, LO);    // f>=0 => result >= LO exactly
    float w = -__logf(fmaf(x, -x, 1.0f));
    float p = erfinv_common(w);
    if (__any_sync(0xffffffffu, w >= 5.0f)) {
        if (w >= 5.0f) p = erfinv_rare(w);
    }
    return p * x;
}

__device__ __forceinline__ float jnorm_from_bits(unsigned bits) {
    return 1.41421356237309515f * jnorm_px(bits);
}

// divergence-safe variant for cold paths
__device__ __forceinline__ float jnorm_safe(unsigned bits) {
    const float LO = -0.99999994f;
    float f = u01(bits);
    float x = fmaf(f, 2.0f, LO);
    float w = -__logf(fmaf(x, -x, 1.0f));
    float p = (w < 5.0f) ? erfinv_common(w) : erfinv_rare(w);
    return 1.41421356237309515f * p * x;
}

__device__ __forceinline__ float jsigmoid(float x) {
    return 1.0f / (1.0f + expf(-x));
}

// ---------------- 256-block barrier (blocks 0..NBLK-1 only) ----------------
__device__ __forceinline__ void gridbar() {
    __syncthreads();
    if (threadIdx.x == 0) {
        __threadfence();
        unsigned gen = *(volatile unsigned*)&g_bar_gen;
        if (atomicAdd(&g_bar_cnt, 1u) == NBLK - 1u) {
            g_bar_cnt = 0u;
            __threadfence();
            atomicAdd(&g_bar_gen, 1u);
        } else {
            while (*(volatile unsigned*)&g_bar_gen == gen) { }
        }
        __threadfence();
    }
    __syncthreads();
}

// one output row of a layer; math identical to R5..R14 (bit-identical params)
template<int K, bool RELU>
__device__ __forceinline__ void enc_row(
        const float* __restrict__ W, const float* __restrict__ b,
        const float* __restrict__ in, float* __restrict__ outp,
        int w, float* sp, int tid) {
    const int KS = K / 4;
    int d = tid & 63, ks = tid >> 6;
    const float* Wr  = W + w * K + ks * KS;
    const float* inp = in + ks * KS * 64 + d;
    float acc = 0.0f;
    #pragma unroll
    for (int j = 0; j < KS; j++)
        acc = fmaf(Wr[j], inp[j * 64], acc);
    sp[tid] = acc;
    __syncthreads();
    if (tid < 64) {
        float v = ((sp[tid] + sp[tid + 64]) + sp[tid + 128]) + sp[tid + 192];
        v += b[w];
        outp[w * 64 + tid] = RELU ? fmaxf(v, 0.0f) : v;
    }
    __syncthreads();
}

// ---------------- the single fused kernel (grid = 6144) ----------------
__global__ void __launch_bounds__(256) mjd_fused(
        float* __restrict__ out,
        const float* __restrict__ x,
        const float* __restrict__ W0, const float* __restrict__ b0,
        const float* __restrict__ W1, const float* __restrict__ b1,
        const float* __restrict__ W2, const float* __restrict__ b2,
        const float* __restrict__ W3, const float* __restrict__ b3,
        const int* __restrict__ seed_ptr) {
    __shared__ float          sp[256];
    __shared__ unsigned short sq[8][QMAX];   // candidate/survivor: m | lane<<8
    __shared__ unsigned       sqb[8][QMAX];  // survivor bits b
    __shared__ float          sjn[8][32];
    __shared__ float          swj[8][32];
    __shared__ uint2          s_sub[NSUB + 2];

    const int t = threadIdx.x, bid = blockIdx.x;
    const int lane = t & 31, wp = t >> 5;
    const unsigned one = g_one;
    const unsigned seed = (unsigned)(*seed_ptr);

    // ================= encoder (blocks 0..255, ONE row per layer) ==========
    if (bid < NBLK) {
        if (bid == NBLK - 1 && t == 0) {
            uint2 key = make_uint2(0u, seed);
            uint2 kp = tf2x32(key.x, key.y, 0u, 1u);
            uint2 rng = kp;
            for (int q = 1; q <= NSUB; q++) {
                uint2 nr = tf2x32(rng.x, rng.y, 0u, 0u);
                g_sub[q] = tf2x32(rng.x, rng.y, 0u, 1u);
                rng = nr;
            }
            __threadfence();
        }

        enc_row<LL,  true>(W0, b0, x,      g_bufA, bid, sp, t);
        gridbar();
        enc_row<WID, true>(W1, b1, g_bufA, g_bufB, bid, sp, t);
        gridbar();
        enc_row<WID, true>(W2, b2, g_bufB, g_bufC, bid, sp, t);
        gridbar();
        if (bid < HH * 5)
            enc_row<WID, false>(W3, b3, g_bufC, g_raw, bid, sp, t);
        gridbar();

        int g = bid * 256 + t;
        if (g < HH * DD) {
            int i = g;
            int d = i & 63, h = i >> 6;
            float mu  = g_raw[(h * 5 + 0) * 64 + d];
            float sg  = jsigmoid(g_raw[(h * 5 + 1) * 64 + d]);
            float ll  = g_raw[(h * 5 + 2) * 64 + d];
            float nuv = tanhf(g_raw[(h * 5 + 3) * 64 + d]) * 0.5f;
            float gmv = jsigmoid(g_raw[(h * 5 + 4) * 64 + d]);
            float lam = expf(fminf(ll, 0.0f));
            float km  = expf(nuv + 0.5f * gmv * gmv) - 1.0f;
            float alpha = (mu - lam * km - 0.5f * sg * sg) * 0.05f;
            g_mu[i]  = mu;
            g_ssd[i] = sg * sqrtf(0.05f);
            g_nu[i]  = nuv;
            g_gm[i]  = gmv;
            g_a20[i] = 20.0f * alpha;
            float mlam = -(lam / 20.0f);
            g_mlam[i] = mlam;
            float ex = expf(mlam);
            int j0 = (int)(ex * 8388608.0f);
            int lo = j0 - 8 < 0 ? 0 : j0 - 8;
            int hi = j0 + 8 > 8388607 ? 8388607 : j0 + 8;
            unsigned jc = 0u;
            for (int j = lo; j <= hi; j++) {
                float u = __uint_as_float(0x3f800000u | (unsigned)j) - 1.0f;
                if (logf(u) <= mlam) jc = (unsigned)j;
            }
            g_bcut[i] = (jc << 9) | 0x1FFu;  // (logf(u)>mlam) == (bits>bcut)
        }
        gridbar();
        if (g < HH * DD) {
            int i = g;
            int d = i & 63, h = i >> 6;
            float c = 0.0f;
            for (int q = 0; q < h; q++) c += g_mu[q * 64 + d];
            float s0 = x[(LL - 1) * 64 + d];
            g_base[i] = ((h == 0) ? s0 : (s0 + c)) + g_a20[i];
        }
        gridbar();
        if (bid == 0 && t == 0) {
            __threadfence();
            atomicExch(&g_flag, 1u);
        }
    }

    // ================= local key derivation (seed-only) =================
    uint2 rk = tf2x32(0u, seed, 0u, (lane < 3) ? (unsigned)lane : 0u);
    unsigned dk0 = __shfl_sync(0xffffffffu, rk.x, 0);
    unsigned dk1 = __shfl_sync(0xffffffffu, rk.y, 0);
    unsigned kpx = __shfl_sync(0xffffffffu, rk.x, 1);
    unsigned kpy = __shfl_sync(0xffffffffu, rk.y, 1);
    unsigned jk0 = __shfl_sync(0xffffffffu, rk.x, 2);
    unsigned jk1 = __shfl_sync(0xffffffffu, rk.y, 2);
    uint2 sub1 = tf2x32(kpx, kpy, 0u, 1u);    // split(k_pois)[1]
    const unsigned sk0 = sub1.x, sk1 = sub1.y, sk2 = sk0 ^ sk1 ^ 0x1BD11BDAu;
    const unsigned dk2 = dk0 ^ dk1 ^ 0x1BD11BDAu;
    const unsigned jk2 = jk0 ^ jk1 ^ 0x1BD11BDAu;

    const int gtid = bid * 256 + t;            // = (k*H + h)*D + d
    const int d  = gtid & (DD - 1);
    const int kh = gtid >> 6;                  // warp-uniform
    const int hd = (kh % HH) * DD + d;
    const unsigned e0 = (unsigned)kh * (MM * DD) + (unsigned)d;
    const unsigned lmask = (1u << lane) - 1u;

    sjn[wp][lane] = 0.0f;
    swj[wp][lane] = 0.0f;

    // ========== phase 1a: diffusion (seed-only; lean loop 1) ==========
    float accd = 0.0f;   // sum of p*x (sqrt2 folded into epilogue)
    {
        unsigned e = e0;
        #pragma unroll 4
        for (int m = 0; m < MM; m++) {
            accd += jnorm_px(tf_bits_pre(dk0, dk1, dk2, e, one));
            e += DD;
        }
    }

    // ========== phase 1b: Poisson candidate bits (seed-only; lean loop 2),
    //            conservative BMIN compare (superset of exact bcut) ==========
    unsigned cmask = 0u;
    {
        unsigned e = e0;
        #pragma unroll 4
        for (int m = 0; m < MM; m++) {
            unsigned b = tf_bits_pre(sk0, sk1, sk2, e, one);
            if (b > BMIN) cmask |= (1u << m);
            e += DD;
        }
    }

    // ---- pre-flag compaction of candidates (shfl prefix sum + ffs) ----
    int c = __popc(cmask);
    int off = c;
    #pragma unroll
    for (int o = 1; o < 32; o <<= 1) {
        int v = __shfl_up_sync(0xffffffffu, off, o);
        if (lane >= o) off += v;
    }
    int pos = off - c;                         // exclusive prefix
    int cnt = __shfl_sync(0xffffffffu, off, 31);
    unsigned ovf = 0u;
    {
        unsigned pm = cmask;
        unsigned lane8 = (unsigned)lane << 8;
        while (pm) {
            int m = __ffs(pm) - 1;
            pm &= pm - 1u;
            if (pos < QMAX) sq[wp][pos] = (unsigned short)(lane8 | (unsigned)m);
            else            ovf |= (1u << m);
            pos++;
        }
    }
    if (cnt > QMAX) cnt = QMAX;
    __syncwarp();

    // ========== wait for encoder results (lane-0 poll + backoff) ==========
    if (lane == 0) {
        while (*(volatile unsigned*)&g_flag == 0u) __nanosleep(128);
    }
    __syncwarp();
    __threadfence();

    const float mlam = __ldcg(&g_mlam[hd]);
    const unsigned bcut = __ldcg(&g_bcut[hd]);
    const float nu  = __ldcg(&g_nu[hd]);
    const float gm  = __ldcg(&g_gm[hd]);
    const float ssd14 = __ldcg(&g_ssd[hd]) * 1.41421356237309515f;
    const float base = __ldcg(&g_base[hd]);
    if (t >= 2 && t <= NSUB) {
        uint2 v; v.x = __ldcg(&g_sub[t].x); v.y = __ldcg(&g_sub[t].y);
        s_sub[t] = v;
    }
    __syncthreads();

    const unsigned ewb = e0 - (unsigned)lane;  // warp-uniform base

    // ===== pass A: recompute candidate bits, exact b>bcut filter =====
    // (~1-2 batches per warp; in-place safe: p2 <= bse+31 < next batch)
    int scnt = 0;
    for (int bse = 0; bse < cnt; bse += 32) {
        int idx = bse + lane;
        bool act = idx < cnt;
        unsigned pk = act ? (unsigned)sq[wp][idx] : 0u;
        int m   = (int)(pk & 0xffu);
        int org = (int)(pk >> 8);
        unsigned ee = ewb + (unsigned)org + (unsigned)(m * DD);
        unsigned b = tf_bits_pre(sk0, sk1, sk2, ee, one);   // same bits
        unsigned bcut_o = __shfl_sync(0xffffffffu, bcut, org);
        bool ev = act && (b > bcut_o);          // EXACT decision
        unsigned bm = __ballot_sync(0xffffffffu, ev);
        if (ev) {
            int p2 = scnt + __popc(bm & lmask);
            sq[wp][p2]  = (unsigned short)pk;
            sqb[wp][p2] = b;
        }
        scnt += __popc(bm);
        __syncwarp();
    }

    // ===== pass B: packed event processing (u1 from stored bits) =====
    for (int bse = 0; bse < scnt; bse += 32) {
        int idx = bse + lane;
        bool act = idx < scnt;
        unsigned pk = act ? (unsigned)sq[wp][idx] : 0u;
        unsigned b  = act ? sqb[wp][idx] : 0u;  // u01(0)=0 -> lp=-inf
        int m   = (int)(pk & 0xffu);
        int org = (int)(pk >> 8);
        unsigned ee = ewb + (unsigned)org + (unsigned)(m * DD);
        float mlam_o = __shfl_sync(0xffffffffu, mlam, org);

        float lp = logf(u01(b));                // precise: decisions match
        float njf = 0.0f;
        int q = 2;
        do {
            lp += logf(u01(tf_bits(s_sub[q], ee)));
            q++; njf += 1.0f;
        } while (lp > mlam_o && q <= NSUB);
        float ej = jnorm_from_bits(tf_bits_pre(jk0, jk1, jk2, ee, one));
        if (act) {
            atomicAdd(&sjn[wp][org], njf);
            atomicAdd(&swj[wp][org], sqrtf(njf) * ej);
        }
    }

    // ---- cold overflow fallback (candidates beyond QMAX; ~never) ----
    float jn_loc = 0.0f, wj_loc = 0.0f;
    if (__any_sync(0xffffffffu, ovf != 0u)) {
        unsigned pm = ovf;
        while (pm) {
            int m = __ffs(pm) - 1;
            pm &= pm - 1u;
            unsigned ee2 = e0 + (unsigned)(m * DD);
            unsigned b = tf_bits(make_uint2(sk0, sk1), ee2);
            if (b > bcut) {
                float lp = logf(u01(b));
                float njf = 0.0f;
                int q = 2;
                do {
                    lp += logf(u01(tf_bits(s_sub[q], ee2)));
                    q++; njf += 1.0f;
                } while (lp > mlam && q <= NSUB);
                jn_loc += njf;
                wj_loc += sqrtf(njf) * jnorm_safe(tf_bits(make_uint2(jk0, jk1), ee2));
            }
        }
    }
    __syncwarp();

    // ========== epilogue ==========
    float jn = jn_loc + sjn[wp][lane];
    float wj = wj_loc + swj[wp][lane];
    out[gtid] = (base + ssd14 * accd) + (nu * jn + gm * wj);
}

// ---------------- launch ----------------
extern "C" void kernel_launch(void* const* d_in, const int* in_sizes, int n_in,
                              void* d_out, int out_size) {
    const float* x  = (const float*)d_in[0];
    const float* W0 = (const float*)d_in[1];
    const float* b0 = (const float*)d_in[2];
    const float* W1 = (const float*)d_in[3];
    const float* b1 = (const float*)d_in[4];
    const float* W2 = (const float*)d_in[5];
    const float* b2 = (const float*)d_in[6];
    const float* W3 = (const float*)d_in[7];
    const float* b3 = (const float*)d_in[8];
    const int* seed = (const int*)d_in[11];
    float* out = (float*)d_out;

    mjd_fused<<<out_size / 256, 256>>>(out, x, W0, b0, W1, b1, W2, b2, W3, b3, seed);
}

// round 16
// speedup vs baseline: 1.1039x; 1.1039x over previous
#include <cuda_runtime.h>
#include <cstdint>

// ---------------------------------------------------------------------------
// NeuralMJDFinancial: exact JAX (threefry-partitionable) reproduction.
// L=96, D=64, H=24, WID=256, K=1024, M=20. Output (K,H,D) f32.
//
// R16 = R14 (227.8us best; pre-flag Poisson family falsified 3x) +
//  * encoder tail consolidated into block 0: params/bcut/base computed by
//    one block with block-level syncs (identical per-item arithmetic);
//    removes 2 contended 256-block grid barriers from the flag critical
//    path and releases blocks 1..255 to MC work after gridbar #4.
// ---------------------------------------------------------------------------

#define DD 64
#define HH 24
#define LL 96
#define WID 256
#define MM 20
#define NSUB 24
#define QMAX 192
#define NBLK 256

__device__ float g_bufA[WID * DD];
__device__ float g_bufB[WID * DD];
__device__ float g_bufC[WID * DD];
__device__ float g_raw[HH * 5 * DD];
__device__ float g_mu[HH * DD];
__device__ float g_base[HH * DD];
__device__ float g_ssd[HH * DD];
__device__ float g_mlam[HH * DD];
__device__ unsigned g_bcut[HH * DD];   // exact decision: bits > bcut
__device__ float g_nu[HH * DD];
__device__ float g_gm[HH * DD];
__device__ float g_a20[HH * DD];
__device__ uint2 g_sub[NSUB + 2];
__device__ unsigned g_bar_cnt;
__device__ unsigned g_bar_gen;
__device__ unsigned g_flag;        // set once encoder results published
__device__ unsigned g_one = 1u;    // opaque 1: forces IMAD (fma pipe)

__device__ __forceinline__ unsigned imad(unsigned a, unsigned b, unsigned c) {
    unsigned r;
    asm("mad.lo.u32 %0, %1, %2, %3;" : "=r"(r) : "r"(a), "r"(b), "r"(c));
    return r;
}

// ---------------- Threefry-2x32, 20 rounds ----------------
// round add on fma pipe (IMAD), rotate SHF (alu), xor LOP3 (alu)
#define TFRI(r) { x0 = imad(x1, one, x0); x1 = __funnelshift_l(x1, x1, (r)); x1 ^= x0; }

// hot variant: x0=0 entry folded (x0=k0, x1=e+k1 via IMAD on fma pipe)
__device__ __forceinline__ unsigned tf_bits_pre(unsigned k0, unsigned k1, unsigned k2,
                                                unsigned e, unsigned one) {
    unsigned x0 = k0;
    unsigned x1 = imad(k1, one, e);
    TFRI(13) TFRI(15) TFRI(26) TFRI(6)
    x0 = imad(k1, one, x0); x1 += k2 + 1u;
    TFRI(17) TFRI(29) TFRI(16) TFRI(24)
    x0 = imad(k2, one, x0); x1 += k0 + 2u;
    TFRI(13) TFRI(15) TFRI(26) TFRI(6)
    x0 = imad(k0, one, x0); x1 += k1 + 3u;
    TFRI(17) TFRI(29) TFRI(16) TFRI(24)
    x0 = imad(k1, one, x0); x1 += k2 + 4u;
    TFRI(13) TFRI(15) TFRI(26) TFRI(6)
    x0 = imad(k2, one, x0); x1 += k0 + 5u;
    return x0 ^ x1;
}

// plain variant (setup / cold / chain)
#define TFR(r) { x0 += x1; x1 = __funnelshift_l(x1, x1, (r)); x1 ^= x0; }

__device__ __forceinline__ uint2 tf2x32(unsigned k0, unsigned k1,
                                        unsigned x0, unsigned x1) {
    unsigned k2 = k0 ^ k1 ^ 0x1BD11BDAu;
    x0 += k0; x1 += k1;
    TFR(13) TFR(15) TFR(26) TFR(6)
    x0 += k1; x1 += k2 + 1u;
    TFR(17) TFR(29) TFR(16) TFR(24)
    x0 += k2; x1 += k0 + 2u;
    TFR(13) TFR(15) TFR(26) TFR(6)
    x0 += k0; x1 += k1 + 3u;
    TFR(17) TFR(29) TFR(16) TFR(24)
    x0 += k1; x1 += k2 + 4u;
    TFR(13) TFR(15) TFR(26) TFR(6)
    x0 += k2; x1 += k0 + 5u;
    return make_uint2(x0, x1);
}

__device__ __forceinline__ unsigned tf_bits(uint2 key, unsigned e) {
    uint2 r = tf2x32(key.x, key.y, 0u, e);
    return r.x ^ r.y;
}

// u01: (b>>9)|0x3f800000 bitcast - 1; shift as IMAD.HI (fma pipe), exact.
__device__ __forceinline__ float u01(unsigned b) {
    unsigned hi = __umulhi(b, 0x00800000u);   // == b >> 9
    return __uint_as_float(hi | 0x3f800000u) - 1.0f;
}

__device__ __forceinline__ float erfinv_common(float w) {
    float ww = w - 2.5f;
    float p = 2.81022636e-08f;
    p = fmaf(p, ww, 3.43273939e-07f);
    p = fmaf(p, ww, -3.5233877e-06f);
    p = fmaf(p, ww, -4.39150654e-06f);
    p = fmaf(p, ww, 0.00021858087f);
    p = fmaf(p, ww, -0.00125372503f);
    p = fmaf(p, ww, -0.00417768164f);
    p = fmaf(p, ww, 0.246640727f);
    p = fmaf(p, ww, 1.50140941f);
    return p;
}

__device__ __forceinline__ float erfinv_rare(float w) {
    float wr = sqrtf(w) - 3.0f;
    float q = -0.000200214257f;
    q = fmaf(q, wr, 0.000100950558f);
    q = fmaf(q, wr, 0.00134934322f);
    q = fmaf(q, wr, -0.00367342844f);
    q = fmaf(q, wr, 0.00573950773f);
    q = fmaf(q, wr, -0.0076224613f);
    q = fmaf(q, wr, 0.00943887047f);
    q = fmaf(q, wr, 1.00167406f);
    q = fmaf(q, wr, 2.83297682f);
    return q;
}

// diffusion normal WITHOUT sqrt2 (folded into epilogue). warp-converged only.
__device__ __forceinline__ float jnorm_px(unsigned bits) {
    const float LO = -0.99999994f;  // 0xBF7FFFFF
    float f = u01(bits);
    float x = fmaf(f, 2.0f, LO);    // f>=0 => result >= LO exactly
    float w = -__logf(fmaf(x, -x, 1.0f));
    float p = erfinv_common(w);
    if (__any_sync(0xffffffffu, w >= 5.0f)) {
        if (w >= 5.0f) p = erfinv_rare(w);
    }
    return p * x;
}

__device__ __forceinline__ float jnorm_from_bits(unsigned bits) {
    return 1.41421356237309515f * jnorm_px(bits);
}

// divergence-safe variant for cold paths
__device__ __forceinline__ float jnorm_safe(unsigned bits) {
    const float LO = -0.99999994f;
    float f = u01(bits);
    float x = fmaf(f, 2.0f, LO);
    float w = -__logf(fmaf(x, -x, 1.0f));
    float p = (w < 5.0f) ? erfinv_common(w) : erfinv_rare(w);
    return 1.41421356237309515f * p * x;
}

__device__ __forceinline__ float jsigmoid(float x) {
    return 1.0f / (1.0f + expf(-x));
}

// ---------------- 256-block barrier (blocks 0..NBLK-1 only) ----------------
__device__ __forceinline__ void gridbar() {
    __syncthreads();
    if (threadIdx.x == 0) {
        __threadfence();
        unsigned gen = *(volatile unsigned*)&g_bar_gen;
        if (atomicAdd(&g_bar_cnt, 1u) == NBLK - 1u) {
            g_bar_cnt = 0u;
            __threadfence();
            atomicAdd(&g_bar_gen, 1u);
        } else {
            while (*(volatile unsigned*)&g_bar_gen == gen) { }
        }
        __threadfence();
    }
    __syncthreads();
}

// one output row of a layer; math identical to R5..R15 (bit-identical params)
template<int K, bool RELU>
__device__ __forceinline__ void enc_row(
        const float* __restrict__ W, const float* __restrict__ b,
        const float* __restrict__ in, float* __restrict__ outp,
        int w, float* sp, int tid) {
    const int KS = K / 4;
    int d = tid & 63, ks = tid >> 6;
    const float* Wr  = W + w * K + ks * KS;
    const float* inp = in + ks * KS * 64 + d;
    float acc = 0.0f;
    #pragma unroll
    for (int j = 0; j < KS; j++)
        acc = fmaf(Wr[j], inp[j * 64], acc);
    sp[tid] = acc;
    __syncthreads();
    if (tid < 64) {
        float v = ((sp[tid] + sp[tid + 64]) + sp[tid + 128]) + sp[tid + 192];
        v += b[w];
        outp[w * 64 + tid] = RELU ? fmaxf(v, 0.0f) : v;
    }
    __syncthreads();
}

// ---------------- the single fused kernel (grid = 6144) ----------------
__global__ void __launch_bounds__(256) mjd_fused(
        float* __restrict__ out,
        const float* __restrict__ x,
        const float* __restrict__ W0, const float* __restrict__ b0,
        const float* __restrict__ W1, const float* __restrict__ b1,
        const float* __restrict__ W2, const float* __restrict__ b2,
        const float* __restrict__ W3, const float* __restrict__ b3,
        const int* __restrict__ seed_ptr) {
    __shared__ float    sp[256];
    __shared__ unsigned sq[8][QMAX];    // packed: m | (origin_lane << 8)
    __shared__ float    sjn[8][32];
    __shared__ float    swj[8][32];
    __shared__ uint2    s_sub[NSUB + 2];

    const int t = threadIdx.x, bid = blockIdx.x;
    const int lane = t & 31, wp = t >> 5;
    const unsigned one = g_one;
    const unsigned seed = (unsigned)(*seed_ptr);

    // ================= encoder (blocks 0..255, ONE row per layer) ==========
    if (bid < NBLK) {
        if (bid == NBLK - 1 && t == 0) {
            uint2 key = make_uint2(0u, seed);
            uint2 kp = tf2x32(key.x, key.y, 0u, 1u);
            uint2 rng = kp;
            for (int q = 1; q <= NSUB; q++) {
                uint2 nr = tf2x32(rng.x, rng.y, 0u, 0u);
                g_sub[q] = tf2x32(rng.x, rng.y, 0u, 1u);
                rng = nr;
            }
            __threadfence();
        }

        enc_row<LL,  true>(W0, b0, x,      g_bufA, bid, sp, t);
        gridbar();
        enc_row<WID, true>(W1, b1, g_bufA, g_bufB, bid, sp, t);
        gridbar();
        enc_row<WID, true>(W2, b2, g_bufB, g_bufC, bid, sp, t);
        gridbar();
        if (bid < HH * 5)
            enc_row<WID, false>(W3, b3, g_bufC, g_raw, bid, sp, t);
        gridbar();   // g_raw complete; blocks 1..255 exit to MC from here

        // ---- block 0 alone: params + bcut + base + flag (block-level syncs)
        if (bid == 0) {
            for (int i = t; i < HH * DD; i += 256) {
                int d = i & 63, h = i >> 6;
                float mu  = g_raw[(h * 5 + 0) * 64 + d];
                float sg  = jsigmoid(g_raw[(h * 5 + 1) * 64 + d]);
                float ll  = g_raw[(h * 5 + 2) * 64 + d];
                float nuv = tanhf(g_raw[(h * 5 + 3) * 64 + d]) * 0.5f;
                float gmv = jsigmoid(g_raw[(h * 5 + 4) * 64 + d]);
                float lam = expf(fminf(ll, 0.0f));
                float km  = expf(nuv + 0.5f * gmv * gmv) - 1.0f;
                float alpha = (mu - lam * km - 0.5f * sg * sg) * 0.05f;
                g_mu[i]  = mu;
                g_ssd[i] = sg * sqrtf(0.05f);
                g_nu[i]  = nuv;
                g_gm[i]  = gmv;
                g_a20[i] = 20.0f * alpha;
                float mlam = -(lam / 20.0f);
                g_mlam[i] = mlam;
                float ex = expf(mlam);
                int j0 = (int)(ex * 8388608.0f);
                int lo = j0 - 8 < 0 ? 0 : j0 - 8;
                int hi = j0 + 8 > 8388607 ? 8388607 : j0 + 8;
                unsigned jc = 0u;
                for (int j = lo; j <= hi; j++) {
                    float u = __uint_as_float(0x3f800000u | (unsigned)j) - 1.0f;
                    if (logf(u) <= mlam) jc = (unsigned)j;
                }
                g_bcut[i] = (jc << 9) | 0x1FFu;  // (logf(u)>mlam)==(bits>bcut)
            }
            __syncthreads();
            for (int i = t; i < HH * DD; i += 256) {
                int d = i & 63, h = i >> 6;
                float c = 0.0f;
                for (int q = 0; q < h; q++) c += g_mu[q * 64 + d];
                float s0 = x[(LL - 1) * 64 + d];
                g_base[i] = ((h == 0) ? s0 : (s0 + c)) + g_a20[i];
            }
            __syncthreads();
            if (t == 0) {
                __threadfence();
                atomicExch(&g_flag, 1u);
            }
        }
    }

    // ================= local key derivation (seed-only) =================
    uint2 rk = tf2x32(0u, seed, 0u, (lane < 3) ? (unsigned)lane : 0u);
    unsigned dk0 = __shfl_sync(0xffffffffu, rk.x, 0);
    unsigned dk1 = __shfl_sync(0xffffffffu, rk.y, 0);
    unsigned kpx = __shfl_sync(0xffffffffu, rk.x, 1);
    unsigned kpy = __shfl_sync(0xffffffffu, rk.y, 1);
    unsigned jk0 = __shfl_sync(0xffffffffu, rk.x, 2);
    unsigned jk1 = __shfl_sync(0xffffffffu, rk.y, 2);
    uint2 sub1 = tf2x32(kpx, kpy, 0u, 1u);    // split(k_pois)[1]
    const unsigned sk0 = sub1.x, sk1 = sub1.y, sk2 = sk0 ^ sk1 ^ 0x1BD11BDAu;
    const unsigned dk2 = dk0 ^ dk1 ^ 0x1BD11BDAu;
    const unsigned jk2 = jk0 ^ jk1 ^ 0x1BD11BDAu;

    const int gtid = bid * 256 + t;            // = (k*H + h)*D + d
    const int d  = gtid & (DD - 1);
    const int kh = gtid >> 6;                  // warp-uniform
    const int hd = (kh % HH) * DD + d;
    const unsigned e0 = (unsigned)kh * (MM * DD) + (unsigned)d;

    sjn[wp][lane] = 0.0f;
    swj[wp][lane] = 0.0f;

    // ========== phase 1a: diffusion (seed-only; overlaps encoder) ==========
    float accd = 0.0f;   // sum of p*x (sqrt2 folded into epilogue)
    {
        unsigned e = e0;
        #pragma unroll 4
        for (int m = 0; m < MM; m++) {
            accd += jnorm_px(tf_bits_pre(dk0, dk1, dk2, e, one));
            e += DD;
        }
    }

    // ========== wait for encoder results (lane-0 poll + backoff) ==========
    if (lane == 0) {
        while (*(volatile unsigned*)&g_flag == 0u) __nanosleep(128);
    }
    __syncwarp();
    __threadfence();

    const float mlam = __ldcg(&g_mlam[hd]);
    const unsigned bcut = __ldcg(&g_bcut[hd]);
    const float nu  = __ldcg(&g_nu[hd]);
    const float gm  = __ldcg(&g_gm[hd]);
    const float ssd14 = __ldcg(&g_ssd[hd]) * 1.41421356237309515f;
    const float base = __ldcg(&g_base[hd]);
    if (t >= 2 && t <= NSUB) {
        uint2 v; v.x = __ldcg(&g_sub[t].x); v.y = __ldcg(&g_sub[t].y);
        s_sub[t] = v;
    }
    __syncthreads();

    // ========== phase 1b: Poisson first-draw bits, exact decision ==========
    unsigned pmask = 0u;
    {
        unsigned e = e0;
        #pragma unroll 4
        for (int m = 0; m < MM; m++) {
            unsigned b = tf_bits_pre(sk0, sk1, sk2, e, one);
            if (b > bcut) pmask |= (1u << m);   // == (logf(u) > mlam)
            e += DD;
        }
    }

    // ---- compact events into per-warp queue (shfl prefix sum) ----
    int c = __popc(pmask);
    int off = c;
    #pragma unroll
    for (int o = 1; o < 32; o <<= 1) {
        int v = __shfl_up_sync(0xffffffffu, off, o);
        if (lane >= o) off += v;
    }
    int pos = off - c;                        // exclusive prefix
    int total = __shfl_sync(0xffffffffu, off, 31);
    float jn_loc = 0.0f, wj_loc = 0.0f;
    unsigned pm = pmask;
    while (pm) {
        int m = __ffs(pm) - 1;
        pm &= pm - 1u;
        if (pos < QMAX) {
            sq[wp][pos] = (unsigned)m | ((unsigned)lane << 8);
        } else {
            // cold overflow fallback (effectively never at these rates)
            unsigned ee2 = e0 + (unsigned)(m * DD);
            float lp = logf(u01(tf_bits(make_uint2(sk0, sk1), ee2)));
            float njf = 0.0f;
            int q = 2;
            do {
                lp += logf(u01(tf_bits(s_sub[q], ee2)));
                q++; njf += 1.0f;
            } while (lp > mlam && q <= NSUB);
            jn_loc += njf;
            wj_loc += sqrtf(njf) * jnorm_safe(tf_bits(make_uint2(jk0, jk1), ee2));
        }
        pos++;
    }
    if (total > QMAX) total = QMAX;
    __syncwarp();

    // ========== phase 2: packed event processing (convergent warp) ==========
    unsigned ewb = e0 - (unsigned)lane;       // warp-uniform base
    for (int bse = 0; bse < total; bse += 32) {
        int idx = bse + lane;
        bool act = idx < total;
        unsigned pk = act ? sq[wp][idx] : 0u;
        int m   = (int)(pk & 0xffu);
        int org = (int)(pk >> 8);
        unsigned ee = ewb + (unsigned)org + (unsigned)(m * DD);
        float mlam_o = __shfl_sync(0xffffffffu, mlam, org);

        float lp = logf(u01(tf_bits_pre(sk0, sk1, sk2, ee, one)));  // same bits
        float njf = 0.0f;
        int q = 2;
        do {
            lp += logf(u01(tf_bits(s_sub[q], ee)));
            q++; njf += 1.0f;
        } while (lp > mlam_o && q <= NSUB);
        float ej = jnorm_from_bits(tf_bits_pre(jk0, jk1, jk2, ee, one));
        if (act) {
            atomicAdd(&sjn[wp][org], njf);
            atomicAdd(&swj[wp][org], sqrtf(njf) * ej);
        }
    }

    __syncwarp();

    // ========== epilogue ==========
    float jn = jn_loc + sjn[wp][lane];
    float wj = wj_loc + swj[wp][lane];
    out[gtid] = (base + ssd14 * accd) + (nu * jn + gm * wj);
}

// ---------------- launch ----------------
extern "C" void kernel_launch(void* const* d_in, const int* in_sizes, int n_in,
                              void* d_out, int out_size) {
    const float* x  = (const float*)d_in[0];
    const float* W0 = (const float*)d_in[1];
    const float* b0 = (const float*)d_in[2];
    const float* W1 = (const float*)d_in[3];
    const float* b1 = (const float*)d_in[4];
    const float* W2 = (const float*)d_in[5];
    const float* b2 = (const float*)d_in[6];
    const float* W3 = (const float*)d_in[7];
    const float* b3 = (const float*)d_in[8];
    const int* seed = (const int*)d_in[11];
    float* out = (float*)d_out;

    mjd_fused<<<out_size / 256, 256>>>(out, x, W0, b0, W1, b1, W2, b2, W3, b3, seed);
}